// round 4
// baseline (speedup 1.0000x reference)
#include <cuda_runtime.h>

#define BB 2
#define LL 2048
#define HH 12
#define DD 64
#define QT 16
#define KT 128                 // tokens per fragment tile
#define NKT (LL / KT)          // 16
#define SK_STRIDE 68
#define SS_STRIDE (LL + 4)     // 2052
#define SP_STRIDE 1028
#define NEWTON_ITERS 6
#define NTHREADS 512
#define ROW_STRIDE (HH * DD)   // 768

// fragment buffers: per (b,h): 256 8-token blocks x 8 ksteps x 32 lanes x float4
#define NF4 (BB * HH * (LL / 8) * 8 * 32)   // 1,572,864 float4 = 25.2 MB
__device__ float4 KFbuf[NF4];
__device__ float4 VFbuf[NF4];

// smem: sQ (16x68) + sF (4096 float4 = 64KB) + sS (16x2052)
#define SF_FLOATS (KT * 64 * 2)            // 16384
#define SMEM_FLOATS (QT * SK_STRIDE + SF_FLOATS + QT * SS_STRIDE)
#define SMEM_BYTES (SMEM_FLOATS * 4)

__device__ __forceinline__ float frcp(float x) {
    float r; asm("rcp.approx.f32 %0, %1;" : "=f"(r) : "f"(x)); return r;
}
__device__ __forceinline__ unsigned f2tf32(float x) {
    unsigned u; asm("cvt.rna.tf32.f32 %0, %1;" : "=r"(u) : "f"(x)); return u;
}
__device__ __forceinline__ void mma8(float4& d,
                                     unsigned a0, unsigned a1, unsigned a2, unsigned a3,
                                     unsigned b0, unsigned b1) {
    asm volatile(
        "mma.sync.aligned.m16n8k8.row.col.f32.tf32.tf32.f32 "
        "{%0,%1,%2,%3}, {%4,%5,%6,%7}, {%8,%9}, {%0,%1,%2,%3};\n"
        : "+f"(d.x), "+f"(d.y), "+f"(d.z), "+f"(d.w)
        : "r"(a0), "r"(a1), "r"(a2), "r"(a3), "r"(b0), "r"(b1));
}

// ---------- pre-pass: Dekker-split K/V into fragment-major layout ----------
__global__ void __launch_bounds__(256)
split_kernel(const float* __restrict__ gk, const float* __restrict__ gv) {
    int idx = blockIdx.x * 256 + threadIdx.x;
    bool isV = idx >= NF4;
    int id   = isV ? idx - NF4 : idx;
    int lane = id & 31;
    int blk2 = (id >> 5) & 7;        // ks (K) or nt (V)
    int blk1 = (id >> 8) & 255;      // token-blk (K) or k-blk (V)
    int bh   = id >> 16;             // 0..23
    int g = lane >> 2, r = lane & 3;
    int b = bh / HH, h = bh % HH;
    const size_t base = (size_t)b * LL * ROW_STRIDE + (size_t)h * DD;

    float x0, x1;
    if (!isV) {
        // K: b0 = K[tb*8+g][ks*8+r], b1 = K[tb*8+g][ks*8+r+4]
        const float* p = gk + base + (size_t)(blk1 * 8 + g) * ROW_STRIDE + blk2 * 8 + r;
        x0 = p[0]; x1 = p[4];
    } else {
        // V: b0 = V[kb*8+r][nt*8+g], b1 = V[kb*8+r+4][nt*8+g]
        const float* p = gv + base + (size_t)(blk1 * 8 + r) * ROW_STRIDE + blk2 * 8 + g;
        x0 = p[0]; x1 = p[4 * ROW_STRIDE];
    }
    unsigned h0 = f2tf32(x0), h1 = f2tf32(x1);
    float4 o;
    o.x = __uint_as_float(h0);
    o.y = x0 - __uint_as_float(h0);
    o.z = __uint_as_float(h1);
    o.w = x1 - __uint_as_float(h1);
    (isV ? VFbuf : KFbuf)[id] = o;
}

extern __shared__ float smem[];

__global__ void __launch_bounds__(NTHREADS, 1)
poly_attn_kernel(const float* __restrict__ gq,
                 float* __restrict__ gout) {
    float*  sQ = smem;
    float4* sF = reinterpret_cast<float4*>(smem + QT * SK_STRIDE);
    float*  sS = smem + QT * SK_STRIDE + SF_FLOATS;

    const int t    = threadIdx.x;
    const int lane = t & 31;
    const int warp = t >> 5;
    const int g    = lane >> 2;
    const int r    = lane & 3;
    const int q0   = blockIdx.x * QT;
    const int h    = blockIdx.y;
    const int b    = blockIdx.z;
    const int bh   = b * HH + h;

    const size_t bh_base = (size_t)b * LL * ROW_STRIDE + (size_t)h * DD;

    // ---- load Q tile (scaled by 0.125) ----
    if (t < QT * 16) {
        int row = t >> 4;
        int c4  = (t & 15) * 4;
        float4 qv = *reinterpret_cast<const float4*>(
            gq + bh_base + (size_t)(q0 + row) * ROW_STRIDE + c4);
        qv.x *= 0.125f; qv.y *= 0.125f; qv.z *= 0.125f; qv.w *= 0.125f;
        *reinterpret_cast<float4*>(sQ + row * SK_STRIDE + c4) = qv;
    }
    __syncthreads();

    // ==== Phase 1: S = Q K^T ====
    {
        unsigned ah[8][4], al[8][4];
        #pragma unroll
        for (int ks = 0; ks < 8; ++ks) {
            int d0 = ks * 8;
            float f0 = sQ[(g    ) * SK_STRIDE + d0 + r];
            float f1 = sQ[(g + 8) * SK_STRIDE + d0 + r];
            float f2 = sQ[(g    ) * SK_STRIDE + d0 + r + 4];
            float f3 = sQ[(g + 8) * SK_STRIDE + d0 + r + 4];
            ah[ks][0] = f2tf32(f0); al[ks][0] = __float_as_uint(f0 - __uint_as_float(ah[ks][0]));
            ah[ks][1] = f2tf32(f1); al[ks][1] = __float_as_uint(f1 - __uint_as_float(ah[ks][1]));
            ah[ks][2] = f2tf32(f2); al[ks][2] = __float_as_uint(f2 - __uint_as_float(ah[ks][2]));
            ah[ks][3] = f2tf32(f3); al[ks][3] = __float_as_uint(f3 - __uint_as_float(ah[ks][3]));
        }

        const float4* kfb = KFbuf + ((size_t)bh * (LL / 8)) * 256;
        for (int kt = 0; kt < NKT; ++kt) {
            const float4* src = kfb + (size_t)kt * 16 * 256;
            #pragma unroll
            for (int i = 0; i < 8; ++i) sF[t + i * NTHREADS] = src[t + i * NTHREADS];
            __syncthreads();

            float4 c1 = make_float4(0.f, 0.f, 0.f, 0.f);
            float4 c2 = make_float4(0.f, 0.f, 0.f, 0.f);
            const float4* fp = sF + warp * 8 * 32 + lane;
            #pragma unroll
            for (int ks = 0; ks < 8; ++ks) {
                float4 bf = fp[ks * 32];
                unsigned b0h = __float_as_uint(bf.x), b0l = __float_as_uint(bf.y);
                unsigned b1h = __float_as_uint(bf.z), b1l = __float_as_uint(bf.w);
                mma8(c1, ah[ks][0], ah[ks][1], ah[ks][2], ah[ks][3], b0h, b1h);
                mma8(c2, ah[ks][0], ah[ks][1], ah[ks][2], ah[ks][3], b0l, b1l);
                mma8(c2, al[ks][0], al[ks][1], al[ks][2], al[ks][3], b0h, b1h);
            }
            c1.x += c2.x; c1.y += c2.y; c1.z += c2.z; c1.w += c2.w;
            int col = kt * KT + warp * 8 + 2 * r;
            *reinterpret_cast<float2*>(sS + (g    ) * SS_STRIDE + col) = make_float2(c1.x, c1.y);
            *reinterpret_cast<float2*>(sS + (g + 8) * SS_STRIDE + col) = make_float2(c1.z, c1.w);
            __syncthreads();
        }
    }

    // ==== Phase 2: poly_norm, one warp per score row ====
    {
        float* srow = sS + warp * SS_STRIDE;
        const float* lp = srow + lane * 4;

        float m = -3.402823466e38f;
        #pragma unroll
        for (int j = 0; j < LL / 128; ++j) {
            float4 v = *reinterpret_cast<const float4*>(lp + j * 128);
            m = fmaxf(m, fmaxf(fmaxf(v.x, v.y), fmaxf(v.z, v.w)));
        }
        #pragma unroll
        for (int o = 16; o; o >>= 1) m = fmaxf(m, __shfl_xor_sync(0xffffffffu, m, o));
        float c = -m - 1.0f;

        for (int it = 0; it < NEWTON_ITERS; ++it) {
            float S = 0.f, Sd = 0.f;
            #pragma unroll
            for (int j = 0; j < LL / 128; ++j) {
                float4 v = *reinterpret_cast<const float4*>(lp + j * 128);
                float i0 = frcp(-v.x - c), i1 = frcp(-v.y - c);
                float i2 = frcp(-v.z - c), i3 = frcp(-v.w - c);
                float s0 = i0*i0, s1 = i1*i1, s2 = i2*i2, s3 = i3*i3;
                S  += (s0 + s1) + (s2 + s3);
                Sd += (s0*i0 + s1*i1) + (s2*i2 + s3*i3);
            }
            #pragma unroll
            for (int o = 16; o; o >>= 1) {
                S  += __shfl_xor_sync(0xffffffffu, S,  o);
                Sd += __shfl_xor_sync(0xffffffffu, Sd, o);
            }
            c = c - (S - 1.0f) / (2.0f * Sd + 1e-8f);
        }

        #pragma unroll
        for (int j = 0; j < LL / 128; ++j) {
            float4 v = *reinterpret_cast<float4*>(srow + lane * 4 + j * 128);
            float i0 = frcp(-v.x - c), i1 = frcp(-v.y - c);
            float i2 = frcp(-v.z - c), i3 = frcp(-v.w - c);
            v.x = i0*i0; v.y = i1*i1; v.z = i2*i2; v.w = i3*i3;
            *reinterpret_cast<float4*>(srow + lane * 4 + j * 128) = v;
        }
    }
    __syncthreads();

    // ==== Phase 3: O = W V, split-k across warps ====
    {
        float4 C[8];
        #pragma unroll
        for (int nt = 0; nt < 8; ++nt) C[nt] = make_float4(0.f, 0.f, 0.f, 0.f);

        const float4* vfb = VFbuf + ((size_t)bh * (LL / 8)) * 256;
        for (int kt = 0; kt < NKT; ++kt) {
            const float4* src = vfb + (size_t)kt * 16 * 256;
            #pragma unroll
            for (int i = 0; i < 8; ++i) sF[t + i * NTHREADS] = src[t + i * NTHREADS];
            __syncthreads();

            int kgl = kt * KT + warp * 8;   // this warp's 8 k-rows
            float w0 = sS[(g    ) * SS_STRIDE + kgl + r];
            float w1 = sS[(g + 8) * SS_STRIDE + kgl + r];
            float w2 = sS[(g    ) * SS_STRIDE + kgl + r + 4];
            float w3 = sS[(g + 8) * SS_STRIDE + kgl + r + 4];
            unsigned ah0 = f2tf32(w0), ah1 = f2tf32(w1);
            unsigned ah2 = f2tf32(w2), ah3 = f2tf32(w3);
            unsigned al0 = __float_as_uint(w0 - __uint_as_float(ah0));
            unsigned al1 = __float_as_uint(w1 - __uint_as_float(ah1));
            unsigned al2 = __float_as_uint(w2 - __uint_as_float(ah2));
            unsigned al3 = __float_as_uint(w3 - __uint_as_float(ah3));

            const float4* vp = sF + warp * 8 * 32 + lane;
            #pragma unroll
            for (int nt = 0; nt < 8; ++nt) {
                float4 bf = vp[nt * 32];
                unsigned b0h = __float_as_uint(bf.x), b0l = __float_as_uint(bf.y);
                unsigned b1h = __float_as_uint(bf.z), b1l = __float_as_uint(bf.w);
                mma8(C[nt], ah0, ah1, ah2, ah3, b0h, b1h);
                mma8(C[nt], ah0, ah1, ah2, ah3, b0l, b1l);
                mma8(C[nt], al0, al1, al2, al3, b0h, b1h);
            }
            __syncthreads();
        }

        // split-k partials into sS (weights fully consumed)
        float* sP = sS;
        #pragma unroll
        for (int nt = 0; nt < 8; ++nt) {
            int d0 = nt * 8 + 2 * r;
            *reinterpret_cast<float2*>(sP + warp * SP_STRIDE + (g    ) * DD + d0) =
                make_float2(C[nt].x, C[nt].y);
            *reinterpret_cast<float2*>(sP + warp * SP_STRIDE + (g + 8) * DD + d0) =
                make_float2(C[nt].z, C[nt].w);
        }
        __syncthreads();

        for (int o = t; o < QT * DD; o += NTHREADS) {
            float s = 0.f;
            #pragma unroll
            for (int w = 0; w < 16; ++w) s += sP[w * SP_STRIDE + o];
            int q  = o >> 6;
            int dc = o & 63;
            gout[bh_base + (size_t)(q0 + q) * ROW_STRIDE + dc] = s;
        }
    }
}

extern "C" void kernel_launch(void* const* d_in, const int* in_sizes, int n_in,
                              void* d_out, int out_size) {
    const float* q = (const float*)d_in[0];
    const float* k = (const float*)d_in[1];
    const float* v = (const float*)d_in[2];
    float* out = (float*)d_out;

    cudaFuncSetAttribute(poly_attn_kernel,
                         cudaFuncAttributeMaxDynamicSharedMemorySize, SMEM_BYTES);

    split_kernel<<<(2 * NF4) / 256, 256>>>(k, v);

    dim3 grid(LL / QT, HH, BB);
    poly_attn_kernel<<<grid, NTHREADS, SMEM_BYTES>>>(q, out);
}

// round 5
// speedup vs baseline: 1.4055x; 1.4055x over previous
#include <cuda_runtime.h>

#define BB 2
#define LL 2048
#define HH 12
#define DD 64
#define NBH (BB * HH)          // 24
#define ROW_STRIDE (HH * DD)   // 768
#define NEWTON_ITERS 6

// ---------------- device scratch ----------------
__device__ float  Sbuf[(size_t)NBH * LL * LL];   // 402 MB scores
__device__ float  Wbuf[(size_t)NBH * LL * LL];   // 402 MB weights
// QF: [bh][mblk 128][ks 8][lane 32][hi/lo f4]  (A-frags of Q, pre-scaled)
__device__ float4 QFbuf[1572864];
// KF: [bh][kblk 256][ks 8][lane 32] f4 = (b0h,b0l,b1h,b1l)
__device__ float4 KFbuf[1572864];
// VF: [bh][kblk 256][nblk 8][lane 32] f4 = (b0h,b0l,b1h,b1l)
__device__ float4 VFbuf[1572864];

#define NQF 786432
#define NKF 1572864
#define NVF 1572864

__device__ __forceinline__ float frcp(float x) {
    float r; asm("rcp.approx.f32 %0, %1;" : "=f"(r) : "f"(x)); return r;
}
__device__ __forceinline__ unsigned f2tf32(float x) {
    unsigned u; asm("cvt.rna.tf32.f32 %0, %1;" : "=r"(u) : "f"(x)); return u;
}
__device__ __forceinline__ void mma8f(float4& d, float4 a, unsigned b0, unsigned b1) {
    asm volatile(
        "mma.sync.aligned.m16n8k8.row.col.f32.tf32.tf32.f32 "
        "{%0,%1,%2,%3}, {%4,%5,%6,%7}, {%8,%9}, {%0,%1,%2,%3};\n"
        : "+f"(d.x), "+f"(d.y), "+f"(d.z), "+f"(d.w)
        : "r"(__float_as_uint(a.x)), "r"(__float_as_uint(a.y)),
          "r"(__float_as_uint(a.z)), "r"(__float_as_uint(a.w)),
          "r"(b0), "r"(b1));
}

// ---------------- prepass: build fragment buffers ----------------
__global__ void __launch_bounds__(256)
prepass_kernel(const float* __restrict__ gq, const float* __restrict__ gk,
               const float* __restrict__ gv) {
    int idx = blockIdx.x * 256 + threadIdx.x;
    int sec, id;
    if (idx < NQF)            { sec = 0; id = idx; }
    else if (idx < NQF + NKF) { sec = 1; id = idx - NQF; }
    else                      { sec = 2; id = idx - NQF - NKF; }
    int lane = id & 31;
    int g = lane >> 2, r = lane & 3;

    if (sec == 0) {
        int ks  = (id >> 5) & 7;
        int blk = (id >> 8) & 127;
        int bh  = id >> 15;
        int b = bh / HH, h = bh - b * HH;
        const size_t base = (size_t)b * LL * ROW_STRIDE + (size_t)h * DD;
        const float* p = gq + base + (size_t)(blk * 16 + g) * ROW_STRIDE + ks * 8 + r;
        float a0 = p[0] * 0.125f;
        float a1 = p[8 * ROW_STRIDE] * 0.125f;
        float a2 = p[4] * 0.125f;
        float a3 = p[8 * ROW_STRIDE + 4] * 0.125f;
        float4 hi, lo;
        hi.x = __uint_as_float(f2tf32(a0)); lo.x = a0 - hi.x;
        hi.y = __uint_as_float(f2tf32(a1)); lo.y = a1 - hi.y;
        hi.z = __uint_as_float(f2tf32(a2)); lo.z = a2 - hi.z;
        hi.w = __uint_as_float(f2tf32(a3)); lo.w = a3 - hi.w;
        QFbuf[(size_t)id * 2]     = hi;
        QFbuf[(size_t)id * 2 + 1] = lo;
    } else {
        int blk2 = (id >> 5) & 7;
        int blk  = (id >> 8) & 255;
        int bh   = id >> 16;
        int b = bh / HH, h = bh - b * HH;
        const size_t base = (size_t)b * LL * ROW_STRIDE + (size_t)h * DD;
        float x0, x1;
        if (sec == 1) {
            const float* p = gk + base + (size_t)(blk * 8 + g) * ROW_STRIDE + blk2 * 8 + r;
            x0 = p[0]; x1 = p[4];
        } else {
            const float* p = gv + base + (size_t)(blk * 8 + r) * ROW_STRIDE + blk2 * 8 + g;
            x0 = p[0]; x1 = p[4 * ROW_STRIDE];
        }
        float4 o;
        o.x = __uint_as_float(f2tf32(x0)); o.y = x0 - o.x;
        o.z = __uint_as_float(f2tf32(x1)); o.w = x1 - o.z;
        (sec == 1 ? KFbuf : VFbuf)[id] = o;
    }
}

// ---------------- kernel A: S = Q K^T (128q x 64k tile) ----------------
extern __shared__ float4 smemA[];

__global__ void __launch_bounds__(256, 2)
qk_kernel() {
    float4* sQf = smemA;          // 4096 f4 (64KB)
    float4* sKf = smemA + 4096;   // 2048 f4 (32KB)
    const int t = threadIdx.x, lane = t & 31, warp = t >> 5;
    const int g = lane >> 2, r = lane & 3;
    const int kt = blockIdx.x, qt = blockIdx.y, bh = blockIdx.z;

    const float4* qsrc = QFbuf + (size_t)(bh * 128 + qt * 8) * 512;
    const float4* ksrc = KFbuf + (size_t)(bh * 256 + kt * 8) * 256;
    #pragma unroll
    for (int i = 0; i < 16; ++i) sQf[t + i * 256] = qsrc[t + i * 256];
    #pragma unroll
    for (int i = 0; i < 8; ++i)  sKf[t + i * 256] = ksrc[t + i * 256];
    __syncthreads();

    const int mw = warp >> 1, nw = warp & 1;
    float4 C[2][4];
    #pragma unroll
    for (int mb = 0; mb < 2; ++mb)
        #pragma unroll
        for (int nb = 0; nb < 4; ++nb) C[mb][nb] = make_float4(0.f, 0.f, 0.f, 0.f);

    #pragma unroll
    for (int ks = 0; ks < 8; ++ks) {
        float4 qh0 = sQf[(((2 * mw    ) * 8 + ks) * 32 + lane) * 2    ];
        float4 ql0 = sQf[(((2 * mw    ) * 8 + ks) * 32 + lane) * 2 + 1];
        float4 qh1 = sQf[(((2 * mw + 1) * 8 + ks) * 32 + lane) * 2    ];
        float4 ql1 = sQf[(((2 * mw + 1) * 8 + ks) * 32 + lane) * 2 + 1];
        #pragma unroll
        for (int nb = 0; nb < 4; ++nb) {
            float4 kf = sKf[((nw * 4 + nb) * 8 + ks) * 32 + lane];
            unsigned b0h = __float_as_uint(kf.x), b0l = __float_as_uint(kf.y);
            unsigned b1h = __float_as_uint(kf.z), b1l = __float_as_uint(kf.w);
            mma8f(C[0][nb], qh0, b0h, b1h);
            mma8f(C[0][nb], qh0, b0l, b1l);
            mma8f(C[0][nb], ql0, b0h, b1h);
            mma8f(C[1][nb], qh1, b0h, b1h);
            mma8f(C[1][nb], qh1, b0l, b1l);
            mma8f(C[1][nb], ql1, b0h, b1h);
        }
    }

    const int q0 = qt * 128, k0 = kt * 64;
    #pragma unroll
    for (int mb = 0; mb < 2; ++mb)
        #pragma unroll
        for (int nb = 0; nb < 4; ++nb) {
            int row = q0 + (2 * mw + mb) * 16 + g;
            int col = k0 + (nw * 4 + nb) * 8 + 2 * r;
            float* sp = Sbuf + ((size_t)bh * LL + row) * LL + col;
            *reinterpret_cast<float2*>(sp)          = make_float2(C[mb][nb].x, C[mb][nb].y);
            *reinterpret_cast<float2*>(sp + 8 * LL) = make_float2(C[mb][nb].z, C[mb][nb].w);
        }
}

// ---------------- kernel B: Newton poly-norm, warp per row ----------------
__global__ void __launch_bounds__(256)
newton_kernel() {
    const int warp = threadIdx.x >> 5, lane = threadIdx.x & 31;
    const size_t rowid = (size_t)blockIdx.x * 8 + warp;
    const float* srow = Sbuf + rowid * LL;

    float4 v[16];
    #pragma unroll
    for (int s = 0; s < 16; ++s)
        v[s] = *reinterpret_cast<const float4*>(srow + s * 128 + lane * 4);

    float m = -3.402823466e38f;
    #pragma unroll
    for (int s = 0; s < 16; ++s)
        m = fmaxf(m, fmaxf(fmaxf(v[s].x, v[s].y), fmaxf(v[s].z, v[s].w)));
    #pragma unroll
    for (int o = 16; o; o >>= 1) m = fmaxf(m, __shfl_xor_sync(0xffffffffu, m, o));
    float c = -m - 1.0f;

    for (int it = 0; it < NEWTON_ITERS; ++it) {
        float S = 0.f, Sd = 0.f;
        #pragma unroll
        for (int s = 0; s < 16; ++s) {
            float i0 = frcp(-v[s].x - c), i1 = frcp(-v[s].y - c);
            float i2 = frcp(-v[s].z - c), i3 = frcp(-v[s].w - c);
            float s0 = i0*i0, s1 = i1*i1, s2 = i2*i2, s3 = i3*i3;
            S  += (s0 + s1) + (s2 + s3);
            Sd += (s0*i0 + s1*i1) + (s2*i2 + s3*i3);
        }
        #pragma unroll
        for (int o = 16; o; o >>= 1) {
            S  += __shfl_xor_sync(0xffffffffu, S,  o);
            Sd += __shfl_xor_sync(0xffffffffu, Sd, o);
        }
        c = c - (S - 1.0f) / (2.0f * Sd + 1e-8f);
    }

    float* wrow = Wbuf + rowid * LL;
    #pragma unroll
    for (int s = 0; s < 16; ++s) {
        float i0 = frcp(-v[s].x - c), i1 = frcp(-v[s].y - c);
        float i2 = frcp(-v[s].z - c), i3 = frcp(-v[s].w - c);
        float4 w = make_float4(i0*i0, i1*i1, i2*i2, i3*i3);
        *reinterpret_cast<float4*>(wrow + s * 128 + lane * 4) = w;
    }
}

// ---------------- kernel C: O = W V (64q x 64d, k=2048) ----------------
#define CW_STRIDE 132
extern __shared__ float smemC[];

__global__ void __launch_bounds__(256, 2)
wv_kernel(float* __restrict__ gout) {
    float*  sW  = smemC;                                         // 64*132 floats
    float4* sVF = reinterpret_cast<float4*>(smemC + 64 * CW_STRIDE); // 4096 f4

    const int t = threadIdx.x, lane = t & 31, warp = t >> 5;
    const int g = lane >> 2, r = lane & 3;
    const int qt = blockIdx.x, bh = blockIdx.y;
    const int b = bh / HH, h = bh - b * HH;
    const int mw = warp >> 1, nw = warp & 1;

    float4 C[4];
    #pragma unroll
    for (int nb = 0; nb < 4; ++nb) C[nb] = make_float4(0.f, 0.f, 0.f, 0.f);

    const float* wbase = Wbuf + ((size_t)bh * LL + qt * 64) * LL;

    for (int ch = 0; ch < 16; ++ch) {
        #pragma unroll
        for (int i = 0; i < 8; ++i) {
            int idx = t + i * 256;              // 0..2047
            int row = idx >> 5, c4 = (idx & 31) * 4;
            float4 wv = *reinterpret_cast<const float4*>(
                wbase + (size_t)row * LL + ch * 128 + c4);
            *reinterpret_cast<float4*>(sW + row * CW_STRIDE + c4) = wv;
        }
        const float4* vs = VFbuf + (size_t)(bh * 256 + ch * 16) * 256;
        #pragma unroll
        for (int i = 0; i < 16; ++i) sVF[t + i * 256] = vs[t + i * 256];
        __syncthreads();

        #pragma unroll
        for (int kb = 0; kb < 16; ++kb) {
            const float* wp = sW + (mw * 16 + g) * CW_STRIDE + kb * 8 + r;
            float w0 = wp[0];
            float w1 = wp[8 * CW_STRIDE];
            float w2 = wp[4];
            float w3 = wp[8 * CW_STRIDE + 4];
            float4 ah, al;
            ah.x = __uint_as_float(f2tf32(w0)); al.x = w0 - ah.x;
            ah.y = __uint_as_float(f2tf32(w1)); al.y = w1 - ah.y;
            ah.z = __uint_as_float(f2tf32(w2)); al.z = w2 - ah.z;
            ah.w = __uint_as_float(f2tf32(w3)); al.w = w3 - ah.w;
            #pragma unroll
            for (int nb = 0; nb < 4; ++nb) {
                float4 vf = sVF[(kb * 8 + nw * 4 + nb) * 32 + lane];
                unsigned b0h = __float_as_uint(vf.x), b0l = __float_as_uint(vf.y);
                unsigned b1h = __float_as_uint(vf.z), b1l = __float_as_uint(vf.w);
                mma8f(C[nb], ah, b0h, b1h);
                mma8f(C[nb], ah, b0l, b1l);
                mma8f(C[nb], al, b0h, b1h);
            }
        }
        __syncthreads();
    }

    const size_t obase = (size_t)b * LL * ROW_STRIDE + (size_t)h * DD;
    #pragma unroll
    for (int nb = 0; nb < 4; ++nb) {
        int row = qt * 64 + mw * 16 + g;
        int d   = (nw * 4 + nb) * 8 + 2 * r;
        float* op = gout + obase + (size_t)row * ROW_STRIDE + d;
        *reinterpret_cast<float2*>(op)                  = make_float2(C[nb].x, C[nb].y);
        *reinterpret_cast<float2*>(op + 8 * ROW_STRIDE) = make_float2(C[nb].z, C[nb].w);
    }
}

// ---------------- launch ----------------
extern "C" void kernel_launch(void* const* d_in, const int* in_sizes, int n_in,
                              void* d_out, int out_size) {
    const float* q = (const float*)d_in[0];
    const float* k = (const float*)d_in[1];
    const float* v = (const float*)d_in[2];
    float* out = (float*)d_out;

    const int SMEM_A = 6144 * 16;                         // 96 KB
    const int SMEM_C = 64 * CW_STRIDE * 4 + 4096 * 16;    // ~97 KB
    cudaFuncSetAttribute(qk_kernel, cudaFuncAttributeMaxDynamicSharedMemorySize, SMEM_A);
    cudaFuncSetAttribute(wv_kernel, cudaFuncAttributeMaxDynamicSharedMemorySize, SMEM_C);

    prepass_kernel<<<(NQF + NKF + NVF) / 256, 256>>>(q, k, v);

    dim3 gridA(32, 16, NBH);
    qk_kernel<<<gridA, 256, SMEM_A>>>();

    newton_kernel<<<NBH * LL / 8, 256>>>();

    dim3 gridC(32, NBH);
    wv_kernel<<<gridC, 256, SMEM_C>>>(out);
}

// round 6
// speedup vs baseline: 1.4766x; 1.0506x over previous
#include <cuda_runtime.h>

#define BB 2
#define LL 2048
#define HH 12
#define DD 64
#define NBH (BB * HH)          // 24
#define ROW_STRIDE (HH * DD)   // 768
#define NEWTON_ITERS 6

// ---------------- device scratch ----------------
__device__ float  Sbuf[(size_t)NBH * LL * LL];   // 402 MB scores
__device__ float  Cbuf[NBH * LL];                // per-row Newton constant
// QF: [bh][mblk 128][ks 8][lane 32][hi/lo f4]  (A-frags of Q, pre-scaled)
__device__ float4 QFbuf[1572864];
// KF: [bh][kblk 256][ks 8][lane 32] f4 = (b0h,b0l,b1h,b1l)
__device__ float4 KFbuf[1572864];
// VF: [bh][kblk 256][nblk 8][lane 32] f4 = (b0h,b0l,b1h,b1l)
__device__ float4 VFbuf[1572864];

#define NQF 786432
#define NKF 1572864
#define NVF 1572864

__device__ __forceinline__ float frcp(float x) {
    float r; asm("rcp.approx.f32 %0, %1;" : "=f"(r) : "f"(x)); return r;
}
__device__ __forceinline__ unsigned f2tf32(float x) {
    unsigned u; asm("cvt.rna.tf32.f32 %0, %1;" : "=r"(u) : "f"(x)); return u;
}
__device__ __forceinline__ void mma8f(float4& d, float4 a, unsigned b0, unsigned b1) {
    asm volatile(
        "mma.sync.aligned.m16n8k8.row.col.f32.tf32.tf32.f32 "
        "{%0,%1,%2,%3}, {%4,%5,%6,%7}, {%8,%9}, {%0,%1,%2,%3};\n"
        : "+f"(d.x), "+f"(d.y), "+f"(d.z), "+f"(d.w)
        : "r"(__float_as_uint(a.x)), "r"(__float_as_uint(a.y)),
          "r"(__float_as_uint(a.z)), "r"(__float_as_uint(a.w)),
          "r"(b0), "r"(b1));
}

// ---------------- prepass: build fragment buffers ----------------
__global__ void __launch_bounds__(256)
prepass_kernel(const float* __restrict__ gq, const float* __restrict__ gk,
               const float* __restrict__ gv) {
    int idx = blockIdx.x * 256 + threadIdx.x;
    int sec, id;
    if (idx < NQF)            { sec = 0; id = idx; }
    else if (idx < NQF + NKF) { sec = 1; id = idx - NQF; }
    else                      { sec = 2; id = idx - NQF - NKF; }
    int lane = id & 31;
    int g = lane >> 2, r = lane & 3;

    if (sec == 0) {
        int ks  = (id >> 5) & 7;
        int blk = (id >> 8) & 127;
        int bh  = id >> 15;
        int b = bh / HH, h = bh - b * HH;
        const size_t base = (size_t)b * LL * ROW_STRIDE + (size_t)h * DD;
        const float* p = gq + base + (size_t)(blk * 16 + g) * ROW_STRIDE + ks * 8 + r;
        float a0 = p[0] * 0.125f;
        float a1 = p[8 * ROW_STRIDE] * 0.125f;
        float a2 = p[4] * 0.125f;
        float a3 = p[8 * ROW_STRIDE + 4] * 0.125f;
        float4 hi, lo;
        hi.x = __uint_as_float(f2tf32(a0)); lo.x = a0 - hi.x;
        hi.y = __uint_as_float(f2tf32(a1)); lo.y = a1 - hi.y;
        hi.z = __uint_as_float(f2tf32(a2)); lo.z = a2 - hi.z;
        hi.w = __uint_as_float(f2tf32(a3)); lo.w = a3 - hi.w;
        QFbuf[(size_t)id * 2]     = hi;
        QFbuf[(size_t)id * 2 + 1] = lo;
    } else {
        int blk2 = (id >> 5) & 7;
        int blk  = (id >> 8) & 255;
        int bh   = id >> 16;
        int b = bh / HH, h = bh - b * HH;
        const size_t base = (size_t)b * LL * ROW_STRIDE + (size_t)h * DD;
        float x0, x1;
        if (sec == 1) {
            const float* p = gk + base + (size_t)(blk * 8 + g) * ROW_STRIDE + blk2 * 8 + r;
            x0 = p[0]; x1 = p[4];
        } else {
            const float* p = gv + base + (size_t)(blk * 8 + r) * ROW_STRIDE + blk2 * 8 + g;
            x0 = p[0]; x1 = p[4 * ROW_STRIDE];
        }
        float4 o;
        o.x = __uint_as_float(f2tf32(x0)); o.y = x0 - o.x;
        o.z = __uint_as_float(f2tf32(x1)); o.w = x1 - o.z;
        (sec == 1 ? KFbuf : VFbuf)[id] = o;
    }
}

// ---------------- kernel A: S = Q K^T (128q x 64k tile) ----------------
extern __shared__ float4 smemA[];

__global__ void __launch_bounds__(256, 2)
qk_kernel() {
    float4* sQf = smemA;          // 4096 f4 (64KB)
    float4* sKf = smemA + 4096;   // 2048 f4 (32KB)
    const int t = threadIdx.x, lane = t & 31, warp = t >> 5;
    const int g = lane >> 2, r = lane & 3;
    const int kt = blockIdx.x, qt = blockIdx.y, bh = blockIdx.z;

    const float4* qsrc = QFbuf + (size_t)(bh * 128 + qt * 8) * 512;
    const float4* ksrc = KFbuf + (size_t)(bh * 256 + kt * 8) * 256;
    #pragma unroll
    for (int i = 0; i < 16; ++i) sQf[t + i * 256] = qsrc[t + i * 256];
    #pragma unroll
    for (int i = 0; i < 8; ++i)  sKf[t + i * 256] = ksrc[t + i * 256];
    __syncthreads();

    const int mw = warp >> 1, nw = warp & 1;
    float4 C[2][4];
    #pragma unroll
    for (int mb = 0; mb < 2; ++mb)
        #pragma unroll
        for (int nb = 0; nb < 4; ++nb) C[mb][nb] = make_float4(0.f, 0.f, 0.f, 0.f);

    #pragma unroll
    for (int ks = 0; ks < 8; ++ks) {
        float4 qh0 = sQf[(((2 * mw    ) * 8 + ks) * 32 + lane) * 2    ];
        float4 ql0 = sQf[(((2 * mw    ) * 8 + ks) * 32 + lane) * 2 + 1];
        float4 qh1 = sQf[(((2 * mw + 1) * 8 + ks) * 32 + lane) * 2    ];
        float4 ql1 = sQf[(((2 * mw + 1) * 8 + ks) * 32 + lane) * 2 + 1];
        #pragma unroll
        for (int nb = 0; nb < 4; ++nb) {
            float4 kf = sKf[((nw * 4 + nb) * 8 + ks) * 32 + lane];
            unsigned b0h = __float_as_uint(kf.x), b0l = __float_as_uint(kf.y);
            unsigned b1h = __float_as_uint(kf.z), b1l = __float_as_uint(kf.w);
            mma8f(C[0][nb], qh0, b0h, b1h);
            mma8f(C[0][nb], qh0, b0l, b1l);
            mma8f(C[0][nb], ql0, b0h, b1h);
            mma8f(C[1][nb], qh1, b0h, b1h);
            mma8f(C[1][nb], qh1, b0l, b1l);
            mma8f(C[1][nb], ql1, b0h, b1h);
        }
    }

    const int q0 = qt * 128, k0 = kt * 64;
    #pragma unroll
    for (int mb = 0; mb < 2; ++mb)
        #pragma unroll
        for (int nb = 0; nb < 4; ++nb) {
            int row = q0 + (2 * mw + mb) * 16 + g;
            int col = k0 + (nw * 4 + nb) * 8 + 2 * r;
            float* sp = Sbuf + ((size_t)bh * LL + row) * LL + col;
            *reinterpret_cast<float2*>(sp)          = make_float2(C[mb][nb].x, C[mb][nb].y);
            *reinterpret_cast<float2*>(sp + 8 * LL) = make_float2(C[mb][nb].z, C[mb][nb].w);
        }
}

// ---------------- kernel B: Newton -> per-row constant c ----------------
__global__ void __launch_bounds__(256)
newton_kernel() {
    const int warp = threadIdx.x >> 5, lane = threadIdx.x & 31;
    const size_t rowid = (size_t)blockIdx.x * 8 + warp;
    const float* srow = Sbuf + rowid * LL;

    float4 v[16];
    #pragma unroll
    for (int s = 0; s < 16; ++s)
        v[s] = *reinterpret_cast<const float4*>(srow + s * 128 + lane * 4);

    float m = -3.402823466e38f;
    #pragma unroll
    for (int s = 0; s < 16; ++s)
        m = fmaxf(m, fmaxf(fmaxf(v[s].x, v[s].y), fmaxf(v[s].z, v[s].w)));
    #pragma unroll
    for (int o = 16; o; o >>= 1) m = fmaxf(m, __shfl_xor_sync(0xffffffffu, m, o));
    float c = -m - 1.0f;

    for (int it = 0; it < NEWTON_ITERS; ++it) {
        float S = 0.f, Sd = 0.f;
        #pragma unroll
        for (int s = 0; s < 16; ++s) {
            float i0 = frcp(-v[s].x - c), i1 = frcp(-v[s].y - c);
            float i2 = frcp(-v[s].z - c), i3 = frcp(-v[s].w - c);
            float s0 = i0*i0, s1 = i1*i1, s2 = i2*i2, s3 = i3*i3;
            S  += (s0 + s1) + (s2 + s3);
            Sd += (s0*i0 + s1*i1) + (s2*i2 + s3*i3);
        }
        #pragma unroll
        for (int o = 16; o; o >>= 1) {
            S  += __shfl_xor_sync(0xffffffffu, S,  o);
            Sd += __shfl_xor_sync(0xffffffffu, Sd, o);
        }
        c = c - (S - 1.0f) / (2.0f * Sd + 1e-8f);
    }

    if (lane == 0) Cbuf[rowid] = c;
}

// ---------------- kernel C: O = W V, W computed inline from S,c ----------------
// CTA: 64 q-rows x 64 d, k-chunks of 64. 128 threads, 4 warps m32n32.
#define CW_STRIDE 68
extern __shared__ float smemC[];

__global__ void __launch_bounds__(128, 4)
wv_kernel(float* __restrict__ gout) {
    float*  sW  = smemC;                                          // 64*68 floats (17KB)
    float*  sc  = smemC + 64 * CW_STRIDE;                         // 64 floats
    float4* sVF = reinterpret_cast<float4*>(smemC + 64 * CW_STRIDE + 64); // 2048 f4 (32KB)

    const int t = threadIdx.x, lane = t & 31, warp = t >> 5;
    const int g = lane >> 2, r = lane & 3;
    const int qt = blockIdx.x, bh = blockIdx.y;
    const int b = bh / HH, h = bh - b * HH;
    const int mw = warp >> 1, nw = warp & 1;   // 2x2 warp grid of m32n32

    if (t < 64) sc[t] = Cbuf[bh * LL + qt * 64 + t];

    float4 C[2][4];
    #pragma unroll
    for (int mt = 0; mt < 2; ++mt)
        #pragma unroll
        for (int nb = 0; nb < 4; ++nb) C[mt][nb] = make_float4(0.f, 0.f, 0.f, 0.f);

    const float* sbase = Sbuf + ((size_t)bh * LL + qt * 64) * LL;
    __syncthreads();

    for (int ch = 0; ch < 32; ++ch) {
        // stage W chunk: 64 rows x 64 cols, computed from S and c
        #pragma unroll
        for (int i = 0; i < 8; ++i) {
            int idx = t + i * 128;              // 0..1023 f4
            int row = idx >> 4, c4 = (idx & 15) * 4;
            float4 s4 = *reinterpret_cast<const float4*>(
                sbase + (size_t)row * LL + ch * 64 + c4);
            float cc = sc[row];
            float i0 = frcp(-s4.x - cc), i1 = frcp(-s4.y - cc);
            float i2 = frcp(-s4.z - cc), i3 = frcp(-s4.w - cc);
            float4 w4 = make_float4(i0*i0, i1*i1, i2*i2, i3*i3);
            *reinterpret_cast<float4*>(sW + row * CW_STRIDE + c4) = w4;
        }
        // stage V fragments for this 64-token chunk (8 kblk x 8 nblk x 32 lanes)
        const float4* vs = VFbuf + (size_t)(bh * 256 + ch * 8) * 256;
        #pragma unroll
        for (int i = 0; i < 16; ++i) sVF[t + i * 128] = vs[t + i * 128];
        __syncthreads();

        #pragma unroll
        for (int kb = 0; kb < 8; ++kb) {
            float4 ah[2], al[2];
            #pragma unroll
            for (int mt = 0; mt < 2; ++mt) {
                const float* wp = sW + (mw * 32 + mt * 16 + g) * CW_STRIDE + kb * 8 + r;
                float w0 = wp[0];
                float w1 = wp[8 * CW_STRIDE];
                float w2 = wp[4];
                float w3 = wp[8 * CW_STRIDE + 4];
                ah[mt].x = __uint_as_float(f2tf32(w0)); al[mt].x = w0 - ah[mt].x;
                ah[mt].y = __uint_as_float(f2tf32(w1)); al[mt].y = w1 - ah[mt].y;
                ah[mt].z = __uint_as_float(f2tf32(w2)); al[mt].z = w2 - ah[mt].z;
                ah[mt].w = __uint_as_float(f2tf32(w3)); al[mt].w = w3 - ah[mt].w;
            }
            #pragma unroll
            for (int nb = 0; nb < 4; ++nb) {
                float4 vf = sVF[(kb * 8 + nw * 4 + nb) * 32 + lane];
                unsigned b0h = __float_as_uint(vf.x), b0l = __float_as_uint(vf.y);
                unsigned b1h = __float_as_uint(vf.z), b1l = __float_as_uint(vf.w);
                mma8f(C[0][nb], ah[0], b0h, b1h);
                mma8f(C[0][nb], ah[0], b0l, b1l);
                mma8f(C[0][nb], al[0], b0h, b1h);
                mma8f(C[1][nb], ah[1], b0h, b1h);
                mma8f(C[1][nb], ah[1], b0l, b1l);
                mma8f(C[1][nb], al[1], b0h, b1h);
            }
        }
        __syncthreads();
    }

    const size_t obase = (size_t)b * LL * ROW_STRIDE + (size_t)h * DD;
    #pragma unroll
    for (int mt = 0; mt < 2; ++mt)
        #pragma unroll
        for (int nb = 0; nb < 4; ++nb) {
            int row = qt * 64 + mw * 32 + mt * 16 + g;
            int d   = nw * 32 + nb * 8 + 2 * r;
            float* op = gout + obase + (size_t)row * ROW_STRIDE + d;
            *reinterpret_cast<float2*>(op)                  = make_float2(C[mt][nb].x, C[mt][nb].y);
            *reinterpret_cast<float2*>(op + 8 * ROW_STRIDE) = make_float2(C[mt][nb].z, C[mt][nb].w);
        }
}

// ---------------- launch ----------------
extern "C" void kernel_launch(void* const* d_in, const int* in_sizes, int n_in,
                              void* d_out, int out_size) {
    const float* q = (const float*)d_in[0];
    const float* k = (const float*)d_in[1];
    const float* v = (const float*)d_in[2];
    float* out = (float*)d_out;

    const int SMEM_A = 6144 * 16;                               // 96 KB
    const int SMEM_C = (64 * CW_STRIDE + 64) * 4 + 2048 * 16;   // ~49.5 KB
    cudaFuncSetAttribute(qk_kernel, cudaFuncAttributeMaxDynamicSharedMemorySize, SMEM_A);
    cudaFuncSetAttribute(wv_kernel, cudaFuncAttributeMaxDynamicSharedMemorySize, SMEM_C);

    prepass_kernel<<<(NQF + NKF + NVF) / 256, 256>>>(q, k, v);

    dim3 gridA(32, 16, NBH);
    qk_kernel<<<gridA, 256, SMEM_A>>>();

    newton_kernel<<<NBH * LL / 8, 256>>>();

    dim3 gridC(32, NBH);
    wv_kernel<<<gridC, 128, SMEM_C>>>(out);
}

// round 8
// speedup vs baseline: 1.5860x; 1.0741x over previous
#include <cuda_runtime.h>

#define BB 2
#define LL 2048
#define HH 12
#define DD 64
#define NBH (BB * HH)          // 24
#define ROW_STRIDE (HH * DD)   // 768
#define NEWTON_ITERS 6

// ---------------- device scratch ----------------
__device__ float  Sbuf[(size_t)NBH * LL * LL];   // 402 MB scores
__device__ float  Cbuf[NBH * LL];                // per-row Newton constant
// QF: [bh][mblk 128][ks 8][lane 32][hi/lo f4]  (A-frags of Q, pre-scaled)
__device__ float4 QFbuf[1572864];
// KF: [bh][kblk 256][ks 8][lane 32] f4 = (b0h,b0l,b1h,b1l)
__device__ float4 KFbuf[1572864];
// VF: [bh][kblk 256][nblk 8][lane 32] f4 = (b0h,b0l,b1h,b1l)
__device__ float4 VFbuf[1572864];

#define NQF 786432
#define NKF 1572864
#define NVF 1572864

__device__ __forceinline__ float frcp(float x) {
    float r; asm("rcp.approx.f32 %0, %1;" : "=f"(r) : "f"(x)); return r;
}
__device__ __forceinline__ unsigned f2tf32(float x) {
    unsigned u; asm("cvt.rna.tf32.f32 %0, %1;" : "=r"(u) : "f"(x)); return u;
}
__device__ __forceinline__ void mma8f(float4& d, float4 a, unsigned b0, unsigned b1) {
    asm volatile(
        "mma.sync.aligned.m16n8k8.row.col.f32.tf32.tf32.f32 "
        "{%0,%1,%2,%3}, {%4,%5,%6,%7}, {%8,%9}, {%0,%1,%2,%3};\n"
        : "+f"(d.x), "+f"(d.y), "+f"(d.z), "+f"(d.w)
        : "r"(__float_as_uint(a.x)), "r"(__float_as_uint(a.y)),
          "r"(__float_as_uint(a.z)), "r"(__float_as_uint(a.w)),
          "r"(b0), "r"(b1));
}

// ---------------- prepass: build fragment buffers ----------------
__global__ void __launch_bounds__(256)
prepass_kernel(const float* __restrict__ gq, const float* __restrict__ gk,
               const float* __restrict__ gv) {
    int idx = blockIdx.x * 256 + threadIdx.x;
    int sec, id;
    if (idx < NQF)            { sec = 0; id = idx; }
    else if (idx < NQF + NKF) { sec = 1; id = idx - NQF; }
    else                      { sec = 2; id = idx - NQF - NKF; }
    int lane = id & 31;
    int g = lane >> 2, r = lane & 3;

    if (sec == 0) {
        int ks  = (id >> 5) & 7;
        int blk = (id >> 8) & 127;
        int bh  = id >> 15;
        int b = bh / HH, h = bh - b * HH;
        const size_t base = (size_t)b * LL * ROW_STRIDE + (size_t)h * DD;
        const float* p = gq + base + (size_t)(blk * 16 + g) * ROW_STRIDE + ks * 8 + r;
        float a0 = p[0] * 0.125f;
        float a1 = p[8 * ROW_STRIDE] * 0.125f;
        float a2 = p[4] * 0.125f;
        float a3 = p[8 * ROW_STRIDE + 4] * 0.125f;
        float4 hi, lo;
        hi.x = __uint_as_float(f2tf32(a0)); lo.x = a0 - hi.x;
        hi.y = __uint_as_float(f2tf32(a1)); lo.y = a1 - hi.y;
        hi.z = __uint_as_float(f2tf32(a2)); lo.z = a2 - hi.z;
        hi.w = __uint_as_float(f2tf32(a3)); lo.w = a3 - hi.w;
        QFbuf[(size_t)id * 2]     = hi;
        QFbuf[(size_t)id * 2 + 1] = lo;
    } else {
        int blk2 = (id >> 5) & 7;
        int blk  = (id >> 8) & 255;
        int bh   = id >> 16;
        int b = bh / HH, h = bh - b * HH;
        const size_t base = (size_t)b * LL * ROW_STRIDE + (size_t)h * DD;
        float x0, x1;
        if (sec == 1) {
            const float* p = gk + base + (size_t)(blk * 8 + g) * ROW_STRIDE + blk2 * 8 + r;
            x0 = p[0]; x1 = p[4];
        } else {
            const float* p = gv + base + (size_t)(blk * 8 + r) * ROW_STRIDE + blk2 * 8 + g;
            x0 = p[0]; x1 = p[4 * ROW_STRIDE];
        }
        float4 o;
        o.x = __uint_as_float(f2tf32(x0)); o.y = x0 - o.x;
        o.z = __uint_as_float(f2tf32(x1)); o.w = x1 - o.z;
        (sec == 1 ? KFbuf : VFbuf)[id] = o;
    }
}

// ---------------- kernel A: S = Q K^T (128q x 64k tile, 3-term tf32) ----------------
extern __shared__ float4 smemA[];

__global__ void __launch_bounds__(256, 2)
qk_kernel() {
    float4* sQf = smemA;          // 4096 f4 (64KB)
    float4* sKf = smemA + 4096;   // 2048 f4 (32KB)
    const int t = threadIdx.x, lane = t & 31, warp = t >> 5;
    const int g = lane >> 2, r = lane & 3;
    const int kt = blockIdx.x, qt = blockIdx.y, bh = blockIdx.z;

    const float4* qsrc = QFbuf + (size_t)(bh * 128 + qt * 8) * 512;
    const float4* ksrc = KFbuf + (size_t)(bh * 256 + kt * 8) * 256;
    #pragma unroll
    for (int i = 0; i < 16; ++i) sQf[t + i * 256] = qsrc[t + i * 256];
    #pragma unroll
    for (int i = 0; i < 8; ++i)  sKf[t + i * 256] = ksrc[t + i * 256];
    __syncthreads();

    const int mw = warp >> 1, nw = warp & 1;
    float4 C[2][4];
    #pragma unroll
    for (int mb = 0; mb < 2; ++mb)
        #pragma unroll
        for (int nb = 0; nb < 4; ++nb) C[mb][nb] = make_float4(0.f, 0.f, 0.f, 0.f);

    #pragma unroll
    for (int ks = 0; ks < 8; ++ks) {
        float4 qh0 = sQf[(((2 * mw    ) * 8 + ks) * 32 + lane) * 2    ];
        float4 ql0 = sQf[(((2 * mw    ) * 8 + ks) * 32 + lane) * 2 + 1];
        float4 qh1 = sQf[(((2 * mw + 1) * 8 + ks) * 32 + lane) * 2    ];
        float4 ql1 = sQf[(((2 * mw + 1) * 8 + ks) * 32 + lane) * 2 + 1];
        #pragma unroll
        for (int nb = 0; nb < 4; ++nb) {
            float4 kf = sKf[((nw * 4 + nb) * 8 + ks) * 32 + lane];
            unsigned b0h = __float_as_uint(kf.x), b0l = __float_as_uint(kf.y);
            unsigned b1h = __float_as_uint(kf.z), b1l = __float_as_uint(kf.w);
            mma8f(C[0][nb], qh0, b0h, b1h);
            mma8f(C[0][nb], qh0, b0l, b1l);
            mma8f(C[0][nb], ql0, b0h, b1h);
            mma8f(C[1][nb], qh1, b0h, b1h);
            mma8f(C[1][nb], qh1, b0l, b1l);
            mma8f(C[1][nb], ql1, b0h, b1h);
        }
    }

    const int q0 = qt * 128, k0 = kt * 64;
    #pragma unroll
    for (int mb = 0; mb < 2; ++mb)
        #pragma unroll
        for (int nb = 0; nb < 4; ++nb) {
            int row = q0 + (2 * mw + mb) * 16 + g;
            int col = k0 + (nw * 4 + nb) * 8 + 2 * r;
            float* sp = Sbuf + ((size_t)bh * LL + row) * LL + col;
            *reinterpret_cast<float2*>(sp)          = make_float2(C[mb][nb].x, C[mb][nb].y);
            *reinterpret_cast<float2*>(sp + 8 * LL) = make_float2(C[mb][nb].z, C[mb][nb].w);
        }
}

// ---------------- kernel B: Newton -> per-row constant c (exact, 6 iters) ----------------
__global__ void __launch_bounds__(256)
newton_kernel() {
    const int warp = threadIdx.x >> 5, lane = threadIdx.x & 31;
    const size_t rowid = (size_t)blockIdx.x * 8 + warp;
    const float* srow = Sbuf + rowid * LL;

    float4 v[16];
    #pragma unroll
    for (int s = 0; s < 16; ++s)
        v[s] = *reinterpret_cast<const float4*>(srow + s * 128 + lane * 4);

    float m = -3.402823466e38f;
    #pragma unroll
    for (int s = 0; s < 16; ++s)
        m = fmaxf(m, fmaxf(fmaxf(v[s].x, v[s].y), fmaxf(v[s].z, v[s].w)));
    #pragma unroll
    for (int o = 16; o; o >>= 1) m = fmaxf(m, __shfl_xor_sync(0xffffffffu, m, o));
    float c = -m - 1.0f;

    for (int it = 0; it < NEWTON_ITERS; ++it) {
        float S = 0.f, Sd = 0.f;
        #pragma unroll
        for (int s = 0; s < 16; ++s) {
            float i0 = frcp(-v[s].x - c), i1 = frcp(-v[s].y - c);
            float i2 = frcp(-v[s].z - c), i3 = frcp(-v[s].w - c);
            float s0 = i0*i0, s1 = i1*i1, s2 = i2*i2, s3 = i3*i3;
            S  += (s0 + s1) + (s2 + s3);
            Sd += (s0*i0 + s1*i1) + (s2*i2 + s3*i3);
        }
        #pragma unroll
        for (int o = 16; o; o >>= 1) {
            S  += __shfl_xor_sync(0xffffffffu, S,  o);
            Sd += __shfl_xor_sync(0xffffffffu, Sd, o);
        }
        c = c - (S - 1.0f) / (2.0f * Sd + 1e-8f);
    }

    if (lane == 0) Cbuf[rowid] = c;
}

// ---------------- kernel C: O = W V (2-term split), W inline from S,c ----------------
#define CW_STRIDE 68
extern __shared__ float smemC[];

__global__ void __launch_bounds__(128, 4)
wv_kernel(float* __restrict__ gout) {
    float*  sW  = smemC;                                          // 64*68 floats
    float*  sc  = smemC + 64 * CW_STRIDE;                         // 64 floats
    float4* sVF = reinterpret_cast<float4*>(smemC + 64 * CW_STRIDE + 64); // 2048 f4

    const int t = threadIdx.x, lane = t & 31, warp = t >> 5;
    const int g = lane >> 2, r = lane & 3;
    const int qt = blockIdx.x, bh = blockIdx.y;
    const int b = bh / HH, h = bh - b * HH;
    const int mw = warp >> 1, nw = warp & 1;   // 2x2 warp grid of m32n32

    if (t < 64) sc[t] = Cbuf[bh * LL + qt * 64 + t];

    float4 C[2][4];
    #pragma unroll
    for (int mt = 0; mt < 2; ++mt)
        #pragma unroll
        for (int nb = 0; nb < 4; ++nb) C[mt][nb] = make_float4(0.f, 0.f, 0.f, 0.f);

    const float* sbase = Sbuf + ((size_t)bh * LL + qt * 64) * LL;
    __syncthreads();

    for (int ch = 0; ch < 32; ++ch) {
        // stage W chunk: 64 rows x 64 cols, computed from S and c
        #pragma unroll
        for (int i = 0; i < 8; ++i) {
            int idx = t + i * 128;              // 0..1023 f4
            int row = idx >> 4, c4 = (idx & 15) * 4;
            float4 s4 = *reinterpret_cast<const float4*>(
                sbase + (size_t)row * LL + ch * 64 + c4);
            float cc = sc[row];
            float i0 = frcp(-s4.x - cc), i1 = frcp(-s4.y - cc);
            float i2 = frcp(-s4.z - cc), i3 = frcp(-s4.w - cc);
            float4 w4 = make_float4(i0*i0, i1*i1, i2*i2, i3*i3);
            *reinterpret_cast<float4*>(sW + row * CW_STRIDE + c4) = w4;
        }
        // stage V fragments for this 64-token chunk
        const float4* vs = VFbuf + (size_t)(bh * 256 + ch * 8) * 256;
        #pragma unroll
        for (int i = 0; i < 16; ++i) sVF[t + i * 128] = vs[t + i * 128];
        __syncthreads();

        #pragma unroll
        for (int kb = 0; kb < 8; ++kb) {
            float4 ah[2];
            #pragma unroll
            for (int mt = 0; mt < 2; ++mt) {
                const float* wp = sW + (mw * 32 + mt * 16 + g) * CW_STRIDE + kb * 8 + r;
                ah[mt].x = __uint_as_float(f2tf32(wp[0]));
                ah[mt].y = __uint_as_float(f2tf32(wp[8 * CW_STRIDE]));
                ah[mt].z = __uint_as_float(f2tf32(wp[4]));
                ah[mt].w = __uint_as_float(f2tf32(wp[8 * CW_STRIDE + 4]));
            }
            #pragma unroll
            for (int nb = 0; nb < 4; ++nb) {
                float4 vf = sVF[(kb * 8 + nw * 4 + nb) * 32 + lane];
                unsigned b0h = __float_as_uint(vf.x), b0l = __float_as_uint(vf.y);
                unsigned b1h = __float_as_uint(vf.z), b1l = __float_as_uint(vf.w);
                mma8f(C[0][nb], ah[0], b0h, b1h);
                mma8f(C[0][nb], ah[0], b0l, b1l);
                mma8f(C[1][nb], ah[1], b0h, b1h);
                mma8f(C[1][nb], ah[1], b0l, b1l);
            }
        }
        __syncthreads();
    }

    const size_t obase = (size_t)b * LL * ROW_STRIDE + (size_t)h * DD;
    #pragma unroll
    for (int mt = 0; mt < 2; ++mt)
        #pragma unroll
        for (int nb = 0; nb < 4; ++nb) {
            int row = qt * 64 + mw * 32 + mt * 16 + g;
            int d   = nw * 32 + nb * 8 + 2 * r;
            float* op = gout + obase + (size_t)row * ROW_STRIDE + d;
            *reinterpret_cast<float2*>(op)                  = make_float2(C[mt][nb].x, C[mt][nb].y);
            *reinterpret_cast<float2*>(op + 8 * ROW_STRIDE) = make_float2(C[mt][nb].z, C[mt][nb].w);
        }
}

// ---------------- launch ----------------
extern "C" void kernel_launch(void* const* d_in, const int* in_sizes, int n_in,
                              void* d_out, int out_size) {
    const float* q = (const float*)d_in[0];
    const float* k = (const float*)d_in[1];
    const float* v = (const float*)d_in[2];
    float* out = (float*)d_out;

    const int SMEM_A = 6144 * 16;                               // 96 KB
    const int SMEM_C = (64 * CW_STRIDE + 64) * 4 + 2048 * 16;   // ~49.5 KB
    cudaFuncSetAttribute(qk_kernel, cudaFuncAttributeMaxDynamicSharedMemorySize, SMEM_A);
    cudaFuncSetAttribute(wv_kernel, cudaFuncAttributeMaxDynamicSharedMemorySize, SMEM_C);

    prepass_kernel<<<(NQF + NKF + NVF) / 256, 256>>>(q, k, v);

    dim3 gridA(32, 16, NBH);
    qk_kernel<<<gridA, 256, SMEM_A>>>();

    newton_kernel<<<NBH * LL / 8, 256>>>();

    dim3 gridC(32, NBH);
    wv_kernel<<<gridC, 128, SMEM_C>>>(out);
}